// round 5
// baseline (speedup 1.0000x reference)
#include <cuda_runtime.h>
#include <cuda_fp16.h>
#include <math.h>

#define IN_DIM  256
#define HID     64
#define HEADS   4
#define FTOT    256
#define OUT_DIM 10
#define NGRAPH  64
#define MAXN    50000
#define MAXE    800000

// ---------------- static scratch ----------------
__device__ float  g_feat  [MAXN * FTOT];     // GEMM output (fp32, current layer)
__device__ __half g_feat_h[MAXN * FTOT];     // fp16 mirror for edge gather
__device__ float  g_lin   [MAXN * FTOT];     // layer-1 activated output
__device__ float  g_as    [MAXN * HEADS];
__device__ float  g_ad    [MAXN * HEADS];
__device__ int    g_srcdst[2 * MAXE];
__device__ int    g_batch [MAXN];
__device__ int    g_deg   [MAXN];
__device__ int    g_rowptr[MAXN + 1];
__device__ int    g_cursor[MAXN];
__device__ int    g_esrc  [MAXE + MAXN];
__device__ int    g_partial[256];
__device__ float  g_pooled[NGRAPH * HID];
__device__ float  g_cnt   [NGRAPH];

// ---------------- helpers ----------------
__device__ __forceinline__ float lrelu(float v) { return v > 0.f ? v : 0.2f * v; }
__device__ __forceinline__ float elu1(float x)  { return x > 0.f ? x : expm1f(x); }
__device__ __forceinline__ float4 lrelu4(float4 a, float4 b) {
    return make_float4(lrelu(a.x + b.x), lrelu(a.y + b.y),
                       lrelu(a.z + b.z), lrelu(a.w + b.w));
}
__device__ __forceinline__ void max4(float4& m, float4 v) {
    m.x = fmaxf(m.x, v.x); m.y = fmaxf(m.y, v.y);
    m.z = fmaxf(m.z, v.z); m.w = fmaxf(m.w, v.w);
}
__device__ __forceinline__ void red_add_f4(float* addr, float4 v) {
    asm volatile("red.global.add.v4.f32 [%0], {%1, %2, %3, %4};"
                 :: "l"(addr), "f"(v.x), "f"(v.y), "f"(v.z), "f"(v.w)
                 : "memory");
}
__device__ __forceinline__ unsigned f2tf(float x) {
    unsigned r;
    asm("cvt.rna.tf32.f32 %0, %1;" : "=r"(r) : "f"(x));
    return r;
}
__device__ __forceinline__ void mma_tf32(float* c, const unsigned* a, const unsigned* b) {
    asm volatile(
        "mma.sync.aligned.m16n8k8.row.col.f32.tf32.tf32.f32 "
        "{%0,%1,%2,%3},{%4,%5,%6,%7},{%8,%9},{%0,%1,%2,%3};"
        : "+f"(c[0]), "+f"(c[1]), "+f"(c[2]), "+f"(c[3])
        : "r"(a[0]), "r"(a[1]), "r"(a[2]), "r"(a[3]), "r"(b[0]), "r"(b[1]));
}
__device__ __forceinline__ void cp16(void* dst, const void* src, bool pred) {
    unsigned d = (unsigned)__cvta_generic_to_shared(dst);
    int sz = pred ? 16 : 0;
    asm volatile("cp.async.cg.shared.global [%0], [%1], 16, %2;"
                 :: "r"(d), "l"(src), "r"(sz));
}
__device__ __forceinline__ void cp_commit() { asm volatile("cp.async.commit_group;"); }
template <int W> __device__ __forceinline__ void cp_wait() {
    asm volatile("cp.async.wait_group %0;" :: "n"(W));
}

// ---------------- dtype-normalizing converters ----------------
__global__ void convert_edges_kernel(const int* __restrict__ raw, int count) {
    int nz = (raw[2 * threadIdx.x + 1] != 0);
    int any = __syncthreads_or(nz);
    int is64 = !any;
    for (int v = blockIdx.x * blockDim.x + threadIdx.x; v < count;
         v += gridDim.x * blockDim.x)
        g_srcdst[v] = is64 ? raw[2 * v] : raw[v];
}
// batch convert + deg/pooled/cnt init fused
__global__ void convert_batch_init_kernel(const int* __restrict__ raw, int count) {
    int base = count / 2;
    int w = (base | 1) + 2 * threadIdx.x;
    int nz = (raw[w] != 0);
    int any = __syncthreads_or(nz);
    int is64 = !any;
    for (int v = blockIdx.x * blockDim.x + threadIdx.x; v < count;
         v += gridDim.x * blockDim.x) {
        g_batch[v] = is64 ? raw[2 * v] : raw[v];
        g_deg[v] = 1;                              // self-loop pre-counted
    }
    int i = blockIdx.x * blockDim.x + threadIdx.x;
    if (i < NGRAPH * HID) g_pooled[i] = 0.f;
    if (i < NGRAPH) g_cnt[i] = 0.f;
}

// ---------------- CSR build ----------------
__global__ void count_kernel(int E) {
    int e = blockIdx.x * blockDim.x + threadIdx.x;
    if (e < E) atomicAdd(&g_deg[g_srcdst[E + e]], 1);
}
__global__ void scan1_kernel(int N) {
    __shared__ int s[256];
    int i = blockIdx.x * 256 + threadIdx.x;
    s[threadIdx.x] = (i < N) ? g_deg[i] : 0;
    __syncthreads();
    for (int off = 128; off; off >>= 1) {
        if (threadIdx.x < off) s[threadIdx.x] += s[threadIdx.x + off];
        __syncthreads();
    }
    if (!threadIdx.x) g_partial[blockIdx.x] = s[0];
}
__global__ void scan2_kernel(int nb) {
    __shared__ int s[256];
    int t = threadIdx.x;
    int v = (t < nb) ? g_partial[t] : 0;
    s[t] = v;
    __syncthreads();
    for (int off = 1; off < 256; off <<= 1) {
        int x = (t >= off) ? s[t - off] : 0;
        __syncthreads();
        s[t] += x;
        __syncthreads();
    }
    if (t < nb) g_partial[t] = s[t] - v;
}
__global__ void scan3_kernel(int N, int Etot) {
    __shared__ int s[256];
    int t = threadIdx.x;
    int i = blockIdx.x * 256 + t;
    int v = (i < N) ? g_deg[i] : 0;
    s[t] = v;
    __syncthreads();
    for (int off = 1; off < 256; off <<= 1) {
        int x = (t >= off) ? s[t - off] : 0;
        __syncthreads();
        s[t] += x;
        __syncthreads();
    }
    int excl = s[t] - v + g_partial[blockIdx.x];
    if (i < N) { g_rowptr[i] = excl; g_cursor[i] = excl; }
    if (i == 0) g_rowptr[N] = Etot;
}
__global__ void fill_kernel(int E, int Etot) {
    int e = blockIdx.x * blockDim.x + threadIdx.x;
    if (e >= Etot) return;
    int s, d;
    if (e < E) { s = g_srcdst[e]; d = g_srcdst[E + e]; }
    else       { s = d = e - E; }
    int pos = atomicAdd(&g_cursor[d], 1);
    g_esrc[pos] = s;
}

// ---------------- TF32 tensor-core GEMM (+ fp16 mirror) ----------------
#define APAD 20
#define BPAD 136
__global__ __launch_bounds__(256, 2) void gemm_tf32_kernel(
    const float* __restrict__ Aext, const float* __restrict__ B, int M, int which)
{
    const float* __restrict__ A = which ? g_lin : Aext;
    float* __restrict__ C = g_feat;

    __shared__ float As[2][128][APAD];
    __shared__ float Bs[2][16][BPAD];

    int t = threadIdx.x;
    int lane = t & 31;
    int wid = t >> 5;
    int wm = (wid & 1) * 64;
    int wn = (wid >> 1) * 32;
    int m0 = blockIdx.y * 128;
    int n0 = blockIdx.x * 128;
    int gid = lane >> 2, tig = lane & 3;

    float cacc[4][4][4];
    #pragma unroll
    for (int a = 0; a < 4; a++)
        #pragma unroll
        for (int b = 0; b < 4; b++)
            #pragma unroll
            for (int k = 0; k < 4; k++) cacc[a][b][k] = 0.f;

#define LOAD_TILES(stage, k0)                                                   \
    {                                                                           \
        _Pragma("unroll")                                                       \
        for (int r = 0; r < 2; r++) {                                           \
            int cA = t + r * 256;                                               \
            int am = cA >> 2, ak = (cA & 3) * 4;                                \
            cp16(&As[stage][am][ak],                                            \
                 &A[(size_t)(m0 + am) * 256 + (k0) + ak], (m0 + am) < M);       \
            int bk = cA >> 5, bn = (cA & 31) * 4;                               \
            cp16(&Bs[stage][bk][bn], &B[((k0) + bk) * 256 + n0 + bn], true);    \
        }                                                                       \
        cp_commit();                                                            \
    }

    LOAD_TILES(0, 0);
    for (int kt = 0; kt < 16; kt++) {
        int s = kt & 1;
        if (kt < 15) { LOAD_TILES(s ^ 1, (kt + 1) * 16); cp_wait<1>(); }
        else         { cp_wait<0>(); }
        __syncthreads();

        #pragma unroll
        for (int k8 = 0; k8 < 2; k8++) {
            int kk = k8 * 8;
            unsigned af[4][4], bf[4][2];
            #pragma unroll
            for (int mt = 0; mt < 4; mt++) {
                int row = wm + mt * 16 + gid;
                af[mt][0] = f2tf(As[s][row][kk + tig]);
                af[mt][1] = f2tf(As[s][row + 8][kk + tig]);
                af[mt][2] = f2tf(As[s][row][kk + tig + 4]);
                af[mt][3] = f2tf(As[s][row + 8][kk + tig + 4]);
            }
            #pragma unroll
            for (int nt = 0; nt < 4; nt++) {
                int col = wn + nt * 8 + gid;
                bf[nt][0] = f2tf(Bs[s][kk + tig][col]);
                bf[nt][1] = f2tf(Bs[s][kk + tig + 4][col]);
            }
            #pragma unroll
            for (int mt = 0; mt < 4; mt++)
                #pragma unroll
                for (int nt = 0; nt < 4; nt++)
                    mma_tf32(cacc[mt][nt], af[mt], bf[nt]);
        }
        __syncthreads();
    }
#undef LOAD_TILES

    #pragma unroll
    for (int mt = 0; mt < 4; mt++) {
        int row = m0 + wm + mt * 16 + gid;
        #pragma unroll
        for (int nt = 0; nt < 4; nt++) {
            int col = n0 + wn + nt * 8 + tig * 2;
            if (row < M) {
                *reinterpret_cast<float2*>(&C[(size_t)row * 256 + col]) =
                    make_float2(cacc[mt][nt][0], cacc[mt][nt][1]);
                *reinterpret_cast<__half2*>(&g_feat_h[(size_t)row * 256 + col]) =
                    __floats2half2_rn(cacc[mt][nt][0], cacc[mt][nt][1]);
            }
            if (row + 8 < M) {
                *reinterpret_cast<float2*>(&C[(size_t)(row + 8) * 256 + col]) =
                    make_float2(cacc[mt][nt][2], cacc[mt][nt][3]);
                *reinterpret_cast<__half2*>(&g_feat_h[(size_t)(row + 8) * 256 + col]) =
                    __floats2half2_rn(cacc[mt][nt][2], cacc[mt][nt][3]);
            }
        }
    }
}

// ---------------- per-node attention coefficients ----------------
__global__ __launch_bounds__(256) void alphas_kernel(
    const float* __restrict__ att_s, const float* __restrict__ att_d, int N)
{
    int w = (blockIdx.x * blockDim.x + threadIdx.x) >> 5;
    int lane = threadIdx.x & 31;
    if (w >= N * HEADS) return;
    int n = w >> 2, hh = w & 3;
    const float* row = g_feat + (size_t)n * FTOT + hh * HID;
    const float* sv = att_s + hh * HID;
    const float* dv = att_d + hh * HID;
    float s = row[lane] * sv[lane] + row[lane + 32] * sv[lane + 32];
    float d = row[lane] * dv[lane] + row[lane + 32] * dv[lane + 32];
    #pragma unroll
    for (int o = 16; o; o >>= 1) {
        s += __shfl_down_sync(0xFFFFFFFFu, s, o);
        d += __shfl_down_sync(0xFFFFFFFFu, d, o);
    }
    if (lane == 0) { g_as[w] = s; g_ad[w] = d; }
}

// ---------------- warp-per-node GAT ----------------
__global__ __launch_bounds__(256) void gat_warp(const float* __restrict__ bias,
                                                int N, int which)
{
    __shared__ int   s_src  [8][64];
    __shared__ float s_alpha[8][64][4];

    int w    = threadIdx.x >> 5;
    int lane = threadIdx.x & 31;
    int n    = blockIdx.x * 8 + w;
    if (n >= N) return;

    int beg = g_rowptr[n], end = g_rowptr[n + 1];
    int deg = end - beg;
    float4 adv = *reinterpret_cast<const float4*>(&g_ad[n * 4]);
    int hh = lane >> 3;

    float4 m4  = make_float4(-1e30f, -1e30f, -1e30f, -1e30f);
    float4 den = make_float4(0.f, 0.f, 0.f, 0.f);

    if (deg <= 64) {
        // ---- fast path: edge logits in registers ----
        int s0 = (lane      < deg) ? g_esrc[beg + lane]      : -1;
        int s1 = (lane + 32 < deg) ? g_esrc[beg + lane + 32] : -1;
        if (lane < deg)      s_src[w][lane]      = s0;
        if (lane + 32 < deg) s_src[w][lane + 32] = s1;
        float4 v0 = make_float4(-1e30f, -1e30f, -1e30f, -1e30f), v1 = v0;
        if (s0 >= 0) v0 = lrelu4(*reinterpret_cast<const float4*>(&g_as[s0 * 4]), adv);
        if (s1 >= 0) v1 = lrelu4(*reinterpret_cast<const float4*>(&g_as[s1 * 4]), adv);
        m4 = v0; max4(m4, v1);
        #pragma unroll
        for (int o = 16; o; o >>= 1) {
            m4.x = fmaxf(m4.x, __shfl_xor_sync(0xFFFFFFFFu, m4.x, o));
            m4.y = fmaxf(m4.y, __shfl_xor_sync(0xFFFFFFFFu, m4.y, o));
            m4.z = fmaxf(m4.z, __shfl_xor_sync(0xFFFFFFFFu, m4.z, o));
            m4.w = fmaxf(m4.w, __shfl_xor_sync(0xFFFFFFFFu, m4.w, o));
        }
        float4 e0 = make_float4(0.f, 0.f, 0.f, 0.f), e1 = e0;
        if (s0 >= 0) e0 = make_float4(__expf(v0.x - m4.x), __expf(v0.y - m4.y),
                                      __expf(v0.z - m4.z), __expf(v0.w - m4.w));
        if (s1 >= 0) e1 = make_float4(__expf(v1.x - m4.x), __expf(v1.y - m4.y),
                                      __expf(v1.z - m4.z), __expf(v1.w - m4.w));
        den = make_float4(e0.x + e1.x, e0.y + e1.y, e0.z + e1.z, e0.w + e1.w);
        #pragma unroll
        for (int o = 16; o; o >>= 1) {
            den.x += __shfl_xor_sync(0xFFFFFFFFu, den.x, o);
            den.y += __shfl_xor_sync(0xFFFFFFFFu, den.y, o);
            den.z += __shfl_xor_sync(0xFFFFFFFFu, den.z, o);
            den.w += __shfl_xor_sync(0xFFFFFFFFu, den.w, o);
        }
        float4 inv = make_float4(1.f / (den.x + 1e-16f), 1.f / (den.y + 1e-16f),
                                 1.f / (den.z + 1e-16f), 1.f / (den.w + 1e-16f));
        if (s0 >= 0)
            *reinterpret_cast<float4*>(&s_alpha[w][lane][0]) =
                make_float4(e0.x * inv.x, e0.y * inv.y, e0.z * inv.z, e0.w * inv.w);
        if (s1 >= 0)
            *reinterpret_cast<float4*>(&s_alpha[w][lane + 32][0]) =
                make_float4(e1.x * inv.x, e1.y * inv.y, e1.z * inv.z, e1.w * inv.w);
        __syncwarp();

        // ---- aggregation: 8-edge unrolled fp16 gather (MLP=8) ----
        float acc[8] = {0.f, 0.f, 0.f, 0.f, 0.f, 0.f, 0.f, 0.f};
        const __half* __restrict__ H = g_feat_h;
        int j = 0;
        for (; j + 8 <= deg; j += 8) {
            int   ti[8];
            float ai[8];
            uint4 qi[8];
            #pragma unroll
            for (int u = 0; u < 8; u++) {
                ti[u] = s_src[w][j + u];
                ai[u] = s_alpha[w][j + u][hh];
            }
            #pragma unroll
            for (int u = 0; u < 8; u++)
                qi[u] = *reinterpret_cast<const uint4*>(&H[(size_t)ti[u] * FTOT + lane * 8]);
            #pragma unroll
            for (int u = 0; u < 8; u++) {
                #pragma unroll
                for (int p = 0; p < 4; p++) {
                    float2 f = __half22float2(*(reinterpret_cast<const __half2*>(&qi[u]) + p));
                    acc[2*p]   += ai[u] * f.x;
                    acc[2*p+1] += ai[u] * f.y;
                }
            }
        }
        for (; j < deg; j++) {
            int t0 = s_src[w][j];
            float a0 = s_alpha[w][j][hh];
            uint4 q0 = *reinterpret_cast<const uint4*>(&H[(size_t)t0 * FTOT + lane * 8]);
            #pragma unroll
            for (int p = 0; p < 4; p++) {
                float2 f0 = __half22float2(*(reinterpret_cast<const __half2*>(&q0) + p));
                acc[2*p]   += a0 * f0.x;
                acc[2*p+1] += a0 * f0.y;
            }
        }

        // ---- epilogue ----
        if (which == 0) {
            float b[8];
            *reinterpret_cast<float4*>(&b[0]) =
                *reinterpret_cast<const float4*>(&bias[lane * 8]);
            *reinterpret_cast<float4*>(&b[4]) =
                *reinterpret_cast<const float4*>(&bias[lane * 8 + 4]);
            float o[8];
            #pragma unroll
            for (int p = 0; p < 8; p++) o[p] = elu1(acc[p] + b[p]);
            *reinterpret_cast<float4*>(&g_lin[(size_t)n * FTOT + lane * 8]) =
                *reinterpret_cast<const float4*>(&o[0]);
            *reinterpret_cast<float4*>(&g_lin[(size_t)n * FTOT + lane * 8 + 4]) =
                *reinterpret_cast<const float4*>(&o[4]);
        } else {
            #pragma unroll
            for (int p = 0; p < 8; p++) {
                acc[p] += __shfl_xor_sync(0xFFFFFFFFu, acc[p], 8);
                acc[p] += __shfl_xor_sync(0xFFFFFFFFu, acc[p], 16);
            }
            if (lane < 8) {
                int g = g_batch[n];
                float o[8];
                #pragma unroll
                for (int p = 0; p < 8; p++)
                    o[p] = elu1(0.25f * acc[p] + bias[lane * 8 + p]);
                red_add_f4(&g_pooled[g * HID + lane * 8],
                           make_float4(o[0], o[1], o[2], o[3]));
                red_add_f4(&g_pooled[g * HID + lane * 8 + 4],
                           make_float4(o[4], o[5], o[6], o[7]));
                if (lane == 0) atomicAdd(&g_cnt[g], 1.0f);
            }
        }
        return;
    }

    // ---- general path (deg > 64) ----
    for (int c0 = beg; c0 < end; c0 += 64) {
        int cnt = min(64, end - c0);
        int s0 = (lane < cnt) ? g_esrc[c0 + lane] : -1;
        int s1 = (lane + 32 < cnt) ? g_esrc[c0 + lane + 32] : -1;
        if (s0 >= 0) max4(m4, lrelu4(*reinterpret_cast<const float4*>(&g_as[s0 * 4]), adv));
        if (s1 >= 0) max4(m4, lrelu4(*reinterpret_cast<const float4*>(&g_as[s1 * 4]), adv));
    }
    #pragma unroll
    for (int o = 16; o; o >>= 1) {
        m4.x = fmaxf(m4.x, __shfl_xor_sync(0xFFFFFFFFu, m4.x, o));
        m4.y = fmaxf(m4.y, __shfl_xor_sync(0xFFFFFFFFu, m4.y, o));
        m4.z = fmaxf(m4.z, __shfl_xor_sync(0xFFFFFFFFu, m4.z, o));
        m4.w = fmaxf(m4.w, __shfl_xor_sync(0xFFFFFFFFu, m4.w, o));
    }
    for (int c0 = beg; c0 < end; c0 += 64) {
        int cnt = min(64, end - c0);
        int s0 = (lane < cnt) ? g_esrc[c0 + lane] : -1;
        int s1 = (lane + 32 < cnt) ? g_esrc[c0 + lane + 32] : -1;
        if (s0 >= 0) {
            float4 v = lrelu4(*reinterpret_cast<const float4*>(&g_as[s0 * 4]), adv);
            den.x += __expf(v.x - m4.x); den.y += __expf(v.y - m4.y);
            den.z += __expf(v.z - m4.z); den.w += __expf(v.w - m4.w);
        }
        if (s1 >= 0) {
            float4 v = lrelu4(*reinterpret_cast<const float4*>(&g_as[s1 * 4]), adv);
            den.x += __expf(v.x - m4.x); den.y += __expf(v.y - m4.y);
            den.z += __expf(v.z - m4.z); den.w += __expf(v.w - m4.w);
        }
    }
    #pragma unroll
    for (int o = 16; o; o >>= 1) {
        den.x += __shfl_xor_sync(0xFFFFFFFFu, den.x, o);
        den.y += __shfl_xor_sync(0xFFFFFFFFu, den.y, o);
        den.z += __shfl_xor_sync(0xFFFFFFFFu, den.z, o);
        den.w += __shfl_xor_sync(0xFFFFFFFFu, den.w, o);
    }
    float4 inv = make_float4(1.f / (den.x + 1e-16f), 1.f / (den.y + 1e-16f),
                             1.f / (den.z + 1e-16f), 1.f / (den.w + 1e-16f));

    float acc[8] = {0.f, 0.f, 0.f, 0.f, 0.f, 0.f, 0.f, 0.f};
    const __half* __restrict__ H = g_feat_h;
    for (int c0 = beg; c0 < end; c0 += 64) {
        int cnt = min(64, end - c0);
        __syncwarp();
        #pragma unroll
        for (int r = 0; r < 2; r++) {
            int i = lane + r * 32;
            if (i < cnt) {
                int s = g_esrc[c0 + i];
                s_src[w][i] = s;
                float4 v = lrelu4(*reinterpret_cast<const float4*>(&g_as[s * 4]), adv);
                *reinterpret_cast<float4*>(&s_alpha[w][i][0]) =
                    make_float4(__expf(v.x - m4.x) * inv.x, __expf(v.y - m4.y) * inv.y,
                                __expf(v.z - m4.z) * inv.z, __expf(v.w - m4.w) * inv.w);
            }
        }
        __syncwarp();
        int j = 0;
        for (; j + 4 <= cnt; j += 4) {
            int t0 = s_src[w][j], t1 = s_src[w][j+1], t2 = s_src[w][j+2], t3 = s_src[w][j+3];
            float a0 = s_alpha[w][j][hh],   a1 = s_alpha[w][j+1][hh];
            float a2 = s_alpha[w][j+2][hh], a3 = s_alpha[w][j+3][hh];
            uint4 q0 = *reinterpret_cast<const uint4*>(&H[(size_t)t0 * FTOT + lane * 8]);
            uint4 q1 = *reinterpret_cast<const uint4*>(&H[(size_t)t1 * FTOT + lane * 8]);
            uint4 q2 = *reinterpret_cast<const uint4*>(&H[(size_t)t2 * FTOT + lane * 8]);
            uint4 q3 = *reinterpret_cast<const uint4*>(&H[(size_t)t3 * FTOT + lane * 8]);
            #pragma unroll
            for (int p = 0; p < 4; p++) {
                float2 f0 = __half22float2(*(reinterpret_cast<const __half2*>(&q0) + p));
                float2 f1 = __half22float2(*(reinterpret_cast<const __half2*>(&q1) + p));
                float2 f2 = __half22float2(*(reinterpret_cast<const __half2*>(&q2) + p));
                float2 f3 = __half22float2(*(reinterpret_cast<const __half2*>(&q3) + p));
                acc[2*p]   += a0 * f0.x + a1 * f1.x + a2 * f2.x + a3 * f3.x;
                acc[2*p+1] += a0 * f0.y + a1 * f1.y + a2 * f2.y + a3 * f3.y;
            }
        }
        for (; j < cnt; j++) {
            int s = s_src[w][j];
            float a = s_alpha[w][j][hh];
            uint4 q = *reinterpret_cast<const uint4*>(&H[(size_t)s * FTOT + lane * 8]);
            #pragma unroll
            for (int p = 0; p < 4; p++) {
                float2 f = __half22float2(*(reinterpret_cast<const __half2*>(&q) + p));
                acc[2*p]   += a * f.x;
                acc[2*p+1] += a * f.y;
            }
        }
    }

    if (which == 0) {
        float o[8];
        #pragma unroll
        for (int p = 0; p < 8; p++) o[p] = elu1(acc[p] + bias[lane * 8 + p]);
        *reinterpret_cast<float4*>(&g_lin[(size_t)n * FTOT + lane * 8]) =
            *reinterpret_cast<const float4*>(&o[0]);
        *reinterpret_cast<float4*>(&g_lin[(size_t)n * FTOT + lane * 8 + 4]) =
            *reinterpret_cast<const float4*>(&o[4]);
    } else {
        #pragma unroll
        for (int p = 0; p < 8; p++) {
            acc[p] += __shfl_xor_sync(0xFFFFFFFFu, acc[p], 8);
            acc[p] += __shfl_xor_sync(0xFFFFFFFFu, acc[p], 16);
        }
        if (lane < 8) {
            int g = g_batch[n];
            float o[8];
            #pragma unroll
            for (int p = 0; p < 8; p++)
                o[p] = elu1(0.25f * acc[p] + bias[lane * 8 + p]);
            red_add_f4(&g_pooled[g * HID + lane * 8],
                       make_float4(o[0], o[1], o[2], o[3]));
            red_add_f4(&g_pooled[g * HID + lane * 8 + 4],
                       make_float4(o[4], o[5], o[6], o[7]));
            if (lane == 0) atomicAdd(&g_cnt[g], 1.0f);
        }
    }
}

// ---------------- classifier + log_softmax ----------------
__global__ void final_kernel(const float* __restrict__ fcw, const float* __restrict__ fcb,
                             float* __restrict__ out) {
    int g = threadIdx.x;
    if (g >= NGRAPH) return;
    float inv = 1.f / fmaxf(g_cnt[g], 1.f);
    float l[OUT_DIM];
    #pragma unroll
    for (int o = 0; o < OUT_DIM; o++) l[o] = fcb[o];
    for (int c = 0; c < HID; c++) {
        float p = g_pooled[g * HID + c] * inv;
        #pragma unroll
        for (int o = 0; o < OUT_DIM; o++) l[o] = fmaf(p, fcw[c * OUT_DIM + o], l[o]);
    }
    float mx = l[0];
    #pragma unroll
    for (int o = 1; o < OUT_DIM; o++) mx = fmaxf(mx, l[o]);
    float se = 0.f;
    #pragma unroll
    for (int o = 0; o < OUT_DIM; o++) se += expf(l[o] - mx);
    float lse = mx + logf(se);
    #pragma unroll
    for (int o = 0; o < OUT_DIM; o++) out[g * OUT_DIM + o] = l[o] - lse;
}

// ---------------- launch (single stream, capture-proven structure) ----------------
extern "C" void kernel_launch(void* const* d_in, const int* in_sizes, int n_in,
                              void* d_out, int out_size) {
    const float* x   = (const float*)d_in[0];
    const int*   ei  = (const int*)  d_in[1];
    const int*   bat = (const int*)  d_in[2];
    const float* W1  = (const float*)d_in[3];
    const float* as1 = (const float*)d_in[4];
    const float* ad1 = (const float*)d_in[5];
    const float* b1  = (const float*)d_in[6];
    const float* W2  = (const float*)d_in[7];
    const float* as2 = (const float*)d_in[8];
    const float* ad2 = (const float*)d_in[9];
    const float* b2  = (const float*)d_in[10];
    const float* fcw = (const float*)d_in[11];
    const float* fcb = (const float*)d_in[12];
    float* out = (float*)d_out;

    int N    = in_sizes[0] / IN_DIM;
    int E    = in_sizes[1] / 2;
    int Etot = E + N;
    int nb   = (N + 255) / 256;
    const int TB = 256;
    dim3 gemm_grid(2, (N + 127) / 128);
    int gat_blocks = (N + 7) / 8;

    // prologue: converts + CSR build
    convert_edges_kernel     <<<(2 * E + TB - 1) / TB, TB>>>(ei, 2 * E);
    convert_batch_init_kernel<<<nb, TB>>>(bat, N);
    count_kernel<<<(E + TB - 1) / TB, TB>>>(E);
    scan1_kernel<<<nb, TB>>>(N);
    scan2_kernel<<<1, TB>>>(nb);
    scan3_kernel<<<nb, TB>>>(N, Etot);
    fill_kernel <<<(Etot + TB - 1) / TB, TB>>>(E, Etot);

    // layer 1
    gemm_tf32_kernel<<<gemm_grid, TB>>>(x, W1, N, 0);
    alphas_kernel   <<<(N * HEADS * 32 + TB - 1) / TB, TB>>>(as1, ad1, N);
    gat_warp        <<<gat_blocks, TB>>>(b1, N, 0);

    // layer 2
    gemm_tf32_kernel<<<gemm_grid, TB>>>(nullptr, W2, N, 1);
    alphas_kernel   <<<(N * HEADS * 32 + TB - 1) / TB, TB>>>(as2, ad2, N);
    gat_warp        <<<gat_blocks, TB>>>(b2, N, 1);

    // readout
    final_kernel<<<1, 64>>>(fcw, fcb, out);
}

// round 6
// speedup vs baseline: 1.0256x; 1.0256x over previous
#include <cuda_runtime.h>
#include <cuda_fp16.h>
#include <math.h>

#define IN_DIM  256
#define HID     64
#define HEADS   4
#define FTOT    256
#define OUT_DIM 10
#define NGRAPH  64
#define MAXN    50000
#define MAXE    800000

// ---------------- static scratch ----------------
__device__ float  g_feat  [MAXN * FTOT];     // GEMM output (fp32, current layer)
__device__ __half g_feat_h[MAXN * FTOT];     // fp16 mirror for edge gather
__device__ float  g_lin   [MAXN * FTOT];     // layer-1 activated output
__device__ float  g_as    [MAXN * HEADS];
__device__ float  g_ad    [MAXN * HEADS];
__device__ int    g_srcdst[2 * MAXE];
__device__ int    g_batch [MAXN];
__device__ int    g_deg   [MAXN];
__device__ int    g_rowptr[MAXN + 1];
__device__ int    g_cursor[MAXN];
__device__ int    g_esrc  [MAXE + MAXN];
__device__ int    g_partial[256];
__device__ float  g_pooled[NGRAPH * HID];
__device__ float  g_cnt   [NGRAPH];

// ---------------- helpers ----------------
__device__ __forceinline__ float lrelu(float v) { return v > 0.f ? v : 0.2f * v; }
__device__ __forceinline__ float elu1(float x)  { return x > 0.f ? x : expm1f(x); }
__device__ __forceinline__ float4 lrelu4(float4 a, float4 b) {
    return make_float4(lrelu(a.x + b.x), lrelu(a.y + b.y),
                       lrelu(a.z + b.z), lrelu(a.w + b.w));
}
__device__ __forceinline__ void max4(float4& m, float4 v) {
    m.x = fmaxf(m.x, v.x); m.y = fmaxf(m.y, v.y);
    m.z = fmaxf(m.z, v.z); m.w = fmaxf(m.w, v.w);
}
__device__ __forceinline__ void red_add_f4(float* addr, float4 v) {
    asm volatile("red.global.add.v4.f32 [%0], {%1, %2, %3, %4};"
                 :: "l"(addr), "f"(v.x), "f"(v.y), "f"(v.z), "f"(v.w)
                 : "memory");
}
__device__ __forceinline__ void mma_tf32(float* c, const unsigned* a, const unsigned* b) {
    asm volatile(
        "mma.sync.aligned.m16n8k8.row.col.f32.tf32.tf32.f32 "
        "{%0,%1,%2,%3},{%4,%5,%6,%7},{%8,%9},{%0,%1,%2,%3};"
        : "+f"(c[0]), "+f"(c[1]), "+f"(c[2]), "+f"(c[3])
        : "r"(a[0]), "r"(a[1]), "r"(a[2]), "r"(a[3]), "r"(b[0]), "r"(b[1]));
}
__device__ __forceinline__ void cp16(void* dst, const void* src, bool pred) {
    unsigned d = (unsigned)__cvta_generic_to_shared(dst);
    int sz = pred ? 16 : 0;
    asm volatile("cp.async.cg.shared.global [%0], [%1], 16, %2;"
                 :: "r"(d), "l"(src), "r"(sz));
}
__device__ __forceinline__ void cp_commit() { asm volatile("cp.async.commit_group;"); }
template <int W> __device__ __forceinline__ void cp_wait() {
    asm volatile("cp.async.wait_group %0;" :: "n"(W));
}

// ---------------- dtype-normalizing converters ----------------
__global__ void convert_edges_kernel(const int* __restrict__ raw, int count) {
    int nz = (raw[2 * threadIdx.x + 1] != 0);
    int any = __syncthreads_or(nz);
    int is64 = !any;
    for (int v = blockIdx.x * blockDim.x + threadIdx.x; v < count;
         v += gridDim.x * blockDim.x)
        g_srcdst[v] = is64 ? raw[2 * v] : raw[v];
}
// batch convert + deg/pooled/cnt init fused
__global__ void convert_batch_init_kernel(const int* __restrict__ raw, int count) {
    int base = count / 2;
    int w = (base | 1) + 2 * threadIdx.x;
    int nz = (raw[w] != 0);
    int any = __syncthreads_or(nz);
    int is64 = !any;
    for (int v = blockIdx.x * blockDim.x + threadIdx.x; v < count;
         v += gridDim.x * blockDim.x) {
        g_batch[v] = is64 ? raw[2 * v] : raw[v];
        g_deg[v] = 1;                              // self-loop pre-counted
    }
    int i = blockIdx.x * blockDim.x + threadIdx.x;
    if (i < NGRAPH * HID) g_pooled[i] = 0.f;
    if (i < NGRAPH) g_cnt[i] = 0.f;
}

// ---------------- CSR build ----------------
__global__ void count_kernel(int E) {
    int e = blockIdx.x * blockDim.x + threadIdx.x;
    if (e < E) atomicAdd(&g_deg[g_srcdst[E + e]], 1);
}
__global__ void scan1_kernel(int N) {
    __shared__ int s[256];
    int i = blockIdx.x * 256 + threadIdx.x;
    s[threadIdx.x] = (i < N) ? g_deg[i] : 0;
    __syncthreads();
    for (int off = 128; off; off >>= 1) {
        if (threadIdx.x < off) s[threadIdx.x] += s[threadIdx.x + off];
        __syncthreads();
    }
    if (!threadIdx.x) g_partial[blockIdx.x] = s[0];
}
__global__ void scan2_kernel(int nb) {
    __shared__ int s[256];
    int t = threadIdx.x;
    int v = (t < nb) ? g_partial[t] : 0;
    s[t] = v;
    __syncthreads();
    for (int off = 1; off < 256; off <<= 1) {
        int x = (t >= off) ? s[t - off] : 0;
        __syncthreads();
        s[t] += x;
        __syncthreads();
    }
    if (t < nb) g_partial[t] = s[t] - v;
}
__global__ void scan3_kernel(int N, int Etot) {
    __shared__ int s[256];
    int t = threadIdx.x;
    int i = blockIdx.x * 256 + t;
    int v = (i < N) ? g_deg[i] : 0;
    s[t] = v;
    __syncthreads();
    for (int off = 1; off < 256; off <<= 1) {
        int x = (t >= off) ? s[t - off] : 0;
        __syncthreads();
        s[t] += x;
        __syncthreads();
    }
    int excl = s[t] - v + g_partial[blockIdx.x];
    if (i < N) { g_rowptr[i] = excl; g_cursor[i] = excl; }
    if (i == 0) g_rowptr[N] = Etot;
}
__global__ void fill_kernel(int E, int Etot) {
    int e = blockIdx.x * blockDim.x + threadIdx.x;
    if (e >= Etot) return;
    int s, d;
    if (e < E) { s = g_srcdst[e]; d = g_srcdst[E + e]; }
    else       { s = d = e - E; }
    int pos = atomicAdd(&g_cursor[d], 1);
    g_esrc[pos] = s;
}

// ---------------- TF32 tensor-core GEMM (cvt-free; HW truncates f32->tf32) ----------------
#define APAD 20
#define BPAD 136
__global__ __launch_bounds__(256, 2) void gemm_tf32_kernel(
    const float* __restrict__ Aext, const float* __restrict__ B, int M, int which)
{
    const float* __restrict__ A = which ? g_lin : Aext;
    float* __restrict__ C = g_feat;

    __shared__ float As[2][128][APAD];
    __shared__ float Bs[2][16][BPAD];

    int t = threadIdx.x;
    int lane = t & 31;
    int wid = t >> 5;
    int wm = (wid & 1) * 64;
    int wn = (wid >> 1) * 32;
    int m0 = blockIdx.y * 128;
    int n0 = blockIdx.x * 128;
    int gid = lane >> 2, tig = lane & 3;

    float cacc[4][4][4];
    #pragma unroll
    for (int a = 0; a < 4; a++)
        #pragma unroll
        for (int b = 0; b < 4; b++)
            #pragma unroll
            for (int k = 0; k < 4; k++) cacc[a][b][k] = 0.f;

#define LOAD_TILES(stage, k0)                                                   \
    {                                                                           \
        _Pragma("unroll")                                                       \
        for (int r = 0; r < 2; r++) {                                           \
            int cA = t + r * 256;                                               \
            int am = cA >> 2, ak = (cA & 3) * 4;                                \
            cp16(&As[stage][am][ak],                                            \
                 &A[(size_t)(m0 + am) * 256 + (k0) + ak], (m0 + am) < M);       \
            int bk = cA >> 5, bn = (cA & 31) * 4;                               \
            cp16(&Bs[stage][bk][bn], &B[((k0) + bk) * 256 + n0 + bn], true);    \
        }                                                                       \
        cp_commit();                                                            \
    }

    LOAD_TILES(0, 0);
    for (int kt = 0; kt < 16; kt++) {
        int s = kt & 1;
        if (kt < 15) { LOAD_TILES(s ^ 1, (kt + 1) * 16); cp_wait<1>(); }
        else         { cp_wait<0>(); }
        __syncthreads();

        #pragma unroll
        for (int k8 = 0; k8 < 2; k8++) {
            int kk = k8 * 8;
            unsigned af[4][4], bf[4][2];
            #pragma unroll
            for (int mt = 0; mt < 4; mt++) {
                int row = wm + mt * 16 + gid;
                af[mt][0] = __float_as_uint(As[s][row][kk + tig]);
                af[mt][1] = __float_as_uint(As[s][row + 8][kk + tig]);
                af[mt][2] = __float_as_uint(As[s][row][kk + tig + 4]);
                af[mt][3] = __float_as_uint(As[s][row + 8][kk + tig + 4]);
            }
            #pragma unroll
            for (int nt = 0; nt < 4; nt++) {
                int col = wn + nt * 8 + gid;
                bf[nt][0] = __float_as_uint(Bs[s][kk + tig][col]);
                bf[nt][1] = __float_as_uint(Bs[s][kk + tig + 4][col]);
            }
            #pragma unroll
            for (int mt = 0; mt < 4; mt++)
                #pragma unroll
                for (int nt = 0; nt < 4; nt++)
                    mma_tf32(cacc[mt][nt], af[mt], bf[nt]);
        }
        __syncthreads();
    }
#undef LOAD_TILES

    #pragma unroll
    for (int mt = 0; mt < 4; mt++) {
        int row = m0 + wm + mt * 16 + gid;
        #pragma unroll
        for (int nt = 0; nt < 4; nt++) {
            int col = n0 + wn + nt * 8 + tig * 2;
            if (row < M) {
                *reinterpret_cast<float2*>(&C[(size_t)row * 256 + col]) =
                    make_float2(cacc[mt][nt][0], cacc[mt][nt][1]);
                *reinterpret_cast<__half2*>(&g_feat_h[(size_t)row * 256 + col]) =
                    __floats2half2_rn(cacc[mt][nt][0], cacc[mt][nt][1]);
            }
            if (row + 8 < M) {
                *reinterpret_cast<float2*>(&C[(size_t)(row + 8) * 256 + col]) =
                    make_float2(cacc[mt][nt][2], cacc[mt][nt][3]);
                *reinterpret_cast<__half2*>(&g_feat_h[(size_t)(row + 8) * 256 + col]) =
                    __floats2half2_rn(cacc[mt][nt][2], cacc[mt][nt][3]);
            }
        }
    }
}

// ---------------- per-node attention coefficients ----------------
__global__ __launch_bounds__(256) void alphas_kernel(
    const float* __restrict__ att_s, const float* __restrict__ att_d, int N)
{
    int w = (blockIdx.x * blockDim.x + threadIdx.x) >> 5;
    int lane = threadIdx.x & 31;
    if (w >= N * HEADS) return;
    int n = w >> 2, hh = w & 3;
    const float* row = g_feat + (size_t)n * FTOT + hh * HID;
    const float* sv = att_s + hh * HID;
    const float* dv = att_d + hh * HID;
    float s = row[lane] * sv[lane] + row[lane + 32] * sv[lane + 32];
    float d = row[lane] * dv[lane] + row[lane + 32] * dv[lane + 32];
    #pragma unroll
    for (int o = 16; o; o >>= 1) {
        s += __shfl_down_sync(0xFFFFFFFFu, s, o);
        d += __shfl_down_sync(0xFFFFFFFFu, d, o);
    }
    if (lane == 0) { g_as[w] = s; g_ad[w] = d; }
}

// ---------------- warp-per-node GAT ----------------
__global__ __launch_bounds__(256) void gat_warp(const float* __restrict__ bias,
                                                int N, int which)
{
    __shared__ int   s_src  [8][64];
    __shared__ float s_alpha[8][64][4];

    int w    = threadIdx.x >> 5;
    int lane = threadIdx.x & 31;
    int n    = blockIdx.x * 8 + w;
    if (n >= N) return;

    int beg = g_rowptr[n], end = g_rowptr[n + 1];
    int deg = end - beg;
    float4 adv = *reinterpret_cast<const float4*>(&g_ad[n * 4]);
    int hh = lane >> 3;

    float4 m4  = make_float4(-1e30f, -1e30f, -1e30f, -1e30f);
    float4 den = make_float4(0.f, 0.f, 0.f, 0.f);

    if (deg <= 64) {
        // ---- fast path: edge logits in registers ----
        int s0 = (lane      < deg) ? g_esrc[beg + lane]      : -1;
        int s1 = (lane + 32 < deg) ? g_esrc[beg + lane + 32] : -1;
        if (lane < deg)      s_src[w][lane]      = s0;
        if (lane + 32 < deg) s_src[w][lane + 32] = s1;
        float4 v0 = make_float4(-1e30f, -1e30f, -1e30f, -1e30f), v1 = v0;
        if (s0 >= 0) v0 = lrelu4(*reinterpret_cast<const float4*>(&g_as[s0 * 4]), adv);
        if (s1 >= 0) v1 = lrelu4(*reinterpret_cast<const float4*>(&g_as[s1 * 4]), adv);
        m4 = v0; max4(m4, v1);
        #pragma unroll
        for (int o = 16; o; o >>= 1) {
            m4.x = fmaxf(m4.x, __shfl_xor_sync(0xFFFFFFFFu, m4.x, o));
            m4.y = fmaxf(m4.y, __shfl_xor_sync(0xFFFFFFFFu, m4.y, o));
            m4.z = fmaxf(m4.z, __shfl_xor_sync(0xFFFFFFFFu, m4.z, o));
            m4.w = fmaxf(m4.w, __shfl_xor_sync(0xFFFFFFFFu, m4.w, o));
        }
        float4 e0 = make_float4(0.f, 0.f, 0.f, 0.f), e1 = e0;
        if (s0 >= 0) e0 = make_float4(__expf(v0.x - m4.x), __expf(v0.y - m4.y),
                                      __expf(v0.z - m4.z), __expf(v0.w - m4.w));
        if (s1 >= 0) e1 = make_float4(__expf(v1.x - m4.x), __expf(v1.y - m4.y),
                                      __expf(v1.z - m4.z), __expf(v1.w - m4.w));
        den = make_float4(e0.x + e1.x, e0.y + e1.y, e0.z + e1.z, e0.w + e1.w);
        #pragma unroll
        for (int o = 16; o; o >>= 1) {
            den.x += __shfl_xor_sync(0xFFFFFFFFu, den.x, o);
            den.y += __shfl_xor_sync(0xFFFFFFFFu, den.y, o);
            den.z += __shfl_xor_sync(0xFFFFFFFFu, den.z, o);
            den.w += __shfl_xor_sync(0xFFFFFFFFu, den.w, o);
        }
        float4 inv = make_float4(1.f / (den.x + 1e-16f), 1.f / (den.y + 1e-16f),
                                 1.f / (den.z + 1e-16f), 1.f / (den.w + 1e-16f));
        if (s0 >= 0)
            *reinterpret_cast<float4*>(&s_alpha[w][lane][0]) =
                make_float4(e0.x * inv.x, e0.y * inv.y, e0.z * inv.z, e0.w * inv.w);
        if (s1 >= 0)
            *reinterpret_cast<float4*>(&s_alpha[w][lane + 32][0]) =
                make_float4(e1.x * inv.x, e1.y * inv.y, e1.z * inv.z, e1.w * inv.w);
        __syncwarp();

        // ---- aggregation: 4-edge unrolled fp16 gather ----
        float acc[8] = {0.f, 0.f, 0.f, 0.f, 0.f, 0.f, 0.f, 0.f};
        const __half* __restrict__ H = g_feat_h;
        int j = 0;
        for (; j + 4 <= deg; j += 4) {
            int t0 = s_src[w][j], t1 = s_src[w][j + 1];
            int t2 = s_src[w][j + 2], t3 = s_src[w][j + 3];
            float a0 = s_alpha[w][j][hh],     a1 = s_alpha[w][j + 1][hh];
            float a2 = s_alpha[w][j + 2][hh], a3 = s_alpha[w][j + 3][hh];
            uint4 q0 = *reinterpret_cast<const uint4*>(&H[(size_t)t0 * FTOT + lane * 8]);
            uint4 q1 = *reinterpret_cast<const uint4*>(&H[(size_t)t1 * FTOT + lane * 8]);
            uint4 q2 = *reinterpret_cast<const uint4*>(&H[(size_t)t2 * FTOT + lane * 8]);
            uint4 q3 = *reinterpret_cast<const uint4*>(&H[(size_t)t3 * FTOT + lane * 8]);
            #pragma unroll
            for (int p = 0; p < 4; p++) {
                float2 f0 = __half22float2(*(reinterpret_cast<const __half2*>(&q0) + p));
                float2 f1 = __half22float2(*(reinterpret_cast<const __half2*>(&q1) + p));
                float2 f2 = __half22float2(*(reinterpret_cast<const __half2*>(&q2) + p));
                float2 f3 = __half22float2(*(reinterpret_cast<const __half2*>(&q3) + p));
                acc[2*p]   += a0 * f0.x + a1 * f1.x + a2 * f2.x + a3 * f3.x;
                acc[2*p+1] += a0 * f0.y + a1 * f1.y + a2 * f2.y + a3 * f3.y;
            }
        }
        for (; j < deg; j++) {
            int t0 = s_src[w][j];
            float a0 = s_alpha[w][j][hh];
            uint4 q0 = *reinterpret_cast<const uint4*>(&H[(size_t)t0 * FTOT + lane * 8]);
            #pragma unroll
            for (int p = 0; p < 4; p++) {
                float2 f0 = __half22float2(*(reinterpret_cast<const __half2*>(&q0) + p));
                acc[2*p]   += a0 * f0.x;
                acc[2*p+1] += a0 * f0.y;
            }
        }

        // ---- epilogue ----
        if (which == 0) {
            float b[8];
            *reinterpret_cast<float4*>(&b[0]) =
                *reinterpret_cast<const float4*>(&bias[lane * 8]);
            *reinterpret_cast<float4*>(&b[4]) =
                *reinterpret_cast<const float4*>(&bias[lane * 8 + 4]);
            float o[8];
            #pragma unroll
            for (int p = 0; p < 8; p++) o[p] = elu1(acc[p] + b[p]);
            *reinterpret_cast<float4*>(&g_lin[(size_t)n * FTOT + lane * 8]) =
                *reinterpret_cast<const float4*>(&o[0]);
            *reinterpret_cast<float4*>(&g_lin[(size_t)n * FTOT + lane * 8 + 4]) =
                *reinterpret_cast<const float4*>(&o[4]);
        } else {
            #pragma unroll
            for (int p = 0; p < 8; p++) {
                acc[p] += __shfl_xor_sync(0xFFFFFFFFu, acc[p], 8);
                acc[p] += __shfl_xor_sync(0xFFFFFFFFu, acc[p], 16);
            }
            if (lane < 8) {
                int g = g_batch[n];
                float o[8];
                #pragma unroll
                for (int p = 0; p < 8; p++)
                    o[p] = elu1(0.25f * acc[p] + bias[lane * 8 + p]);
                red_add_f4(&g_pooled[g * HID + lane * 8],
                           make_float4(o[0], o[1], o[2], o[3]));
                red_add_f4(&g_pooled[g * HID + lane * 8 + 4],
                           make_float4(o[4], o[5], o[6], o[7]));
                if (lane == 0) atomicAdd(&g_cnt[g], 1.0f);
            }
        }
        return;
    }

    // ---- general path (deg > 64) ----
    for (int c0 = beg; c0 < end; c0 += 64) {
        int cnt = min(64, end - c0);
        int s0 = (lane < cnt) ? g_esrc[c0 + lane] : -1;
        int s1 = (lane + 32 < cnt) ? g_esrc[c0 + lane + 32] : -1;
        if (s0 >= 0) max4(m4, lrelu4(*reinterpret_cast<const float4*>(&g_as[s0 * 4]), adv));
        if (s1 >= 0) max4(m4, lrelu4(*reinterpret_cast<const float4*>(&g_as[s1 * 4]), adv));
    }
    #pragma unroll
    for (int o = 16; o; o >>= 1) {
        m4.x = fmaxf(m4.x, __shfl_xor_sync(0xFFFFFFFFu, m4.x, o));
        m4.y = fmaxf(m4.y, __shfl_xor_sync(0xFFFFFFFFu, m4.y, o));
        m4.z = fmaxf(m4.z, __shfl_xor_sync(0xFFFFFFFFu, m4.z, o));
        m4.w = fmaxf(m4.w, __shfl_xor_sync(0xFFFFFFFFu, m4.w, o));
    }
    for (int c0 = beg; c0 < end; c0 += 64) {
        int cnt = min(64, end - c0);
        int s0 = (lane < cnt) ? g_esrc[c0 + lane] : -1;
        int s1 = (lane + 32 < cnt) ? g_esrc[c0 + lane + 32] : -1;
        if (s0 >= 0) {
            float4 v = lrelu4(*reinterpret_cast<const float4*>(&g_as[s0 * 4]), adv);
            den.x += __expf(v.x - m4.x); den.y += __expf(v.y - m4.y);
            den.z += __expf(v.z - m4.z); den.w += __expf(v.w - m4.w);
        }
        if (s1 >= 0) {
            float4 v = lrelu4(*reinterpret_cast<const float4*>(&g_as[s1 * 4]), adv);
            den.x += __expf(v.x - m4.x); den.y += __expf(v.y - m4.y);
            den.z += __expf(v.z - m4.z); den.w += __expf(v.w - m4.w);
        }
    }
    #pragma unroll
    for (int o = 16; o; o >>= 1) {
        den.x += __shfl_xor_sync(0xFFFFFFFFu, den.x, o);
        den.y += __shfl_xor_sync(0xFFFFFFFFu, den.y, o);
        den.z += __shfl_xor_sync(0xFFFFFFFFu, den.z, o);
        den.w += __shfl_xor_sync(0xFFFFFFFFu, den.w, o);
    }
    float4 inv = make_float4(1.f / (den.x + 1e-16f), 1.f / (den.y + 1e-16f),
                             1.f / (den.z + 1e-16f), 1.f / (den.w + 1e-16f));

    float acc[8] = {0.f, 0.f, 0.f, 0.f, 0.f, 0.f, 0.f, 0.f};
    const __half* __restrict__ H = g_feat_h;
    for (int c0 = beg; c0 < end; c0 += 64) {
        int cnt = min(64, end - c0);
        __syncwarp();
        #pragma unroll
        for (int r = 0; r < 2; r++) {
            int i = lane + r * 32;
            if (i < cnt) {
                int s = g_esrc[c0 + i];
                s_src[w][i] = s;
                float4 v = lrelu4(*reinterpret_cast<const float4*>(&g_as[s * 4]), adv);
                *reinterpret_cast<float4*>(&s_alpha[w][i][0]) =
                    make_float4(__expf(v.x - m4.x) * inv.x, __expf(v.y - m4.y) * inv.y,
                                __expf(v.z - m4.z) * inv.z, __expf(v.w - m4.w) * inv.w);
            }
        }
        __syncwarp();
        int j = 0;
        for (; j + 4 <= cnt; j += 4) {
            int t0 = s_src[w][j], t1 = s_src[w][j+1], t2 = s_src[w][j+2], t3 = s_src[w][j+3];
            float a0 = s_alpha[w][j][hh],   a1 = s_alpha[w][j+1][hh];
            float a2 = s_alpha[w][j+2][hh], a3 = s_alpha[w][j+3][hh];
            uint4 q0 = *reinterpret_cast<const uint4*>(&H[(size_t)t0 * FTOT + lane * 8]);
            uint4 q1 = *reinterpret_cast<const uint4*>(&H[(size_t)t1 * FTOT + lane * 8]);
            uint4 q2 = *reinterpret_cast<const uint4*>(&H[(size_t)t2 * FTOT + lane * 8]);
            uint4 q3 = *reinterpret_cast<const uint4*>(&H[(size_t)t3 * FTOT + lane * 8]);
            #pragma unroll
            for (int p = 0; p < 4; p++) {
                float2 f0 = __half22float2(*(reinterpret_cast<const __half2*>(&q0) + p));
                float2 f1 = __half22float2(*(reinterpret_cast<const __half2*>(&q1) + p));
                float2 f2 = __half22float2(*(reinterpret_cast<const __half2*>(&q2) + p));
                float2 f3 = __half22float2(*(reinterpret_cast<const __half2*>(&q3) + p));
                acc[2*p]   += a0 * f0.x + a1 * f1.x + a2 * f2.x + a3 * f3.x;
                acc[2*p+1] += a0 * f0.y + a1 * f1.y + a2 * f2.y + a3 * f3.y;
            }
        }
        for (; j < cnt; j++) {
            int s = s_src[w][j];
            float a = s_alpha[w][j][hh];
            uint4 q = *reinterpret_cast<const uint4*>(&H[(size_t)s * FTOT + lane * 8]);
            #pragma unroll
            for (int p = 0; p < 4; p++) {
                float2 f = __half22float2(*(reinterpret_cast<const __half2*>(&q) + p));
                acc[2*p]   += a * f.x;
                acc[2*p+1] += a * f.y;
            }
        }
    }

    if (which == 0) {
        float o[8];
        #pragma unroll
        for (int p = 0; p < 8; p++) o[p] = elu1(acc[p] + bias[lane * 8 + p]);
        *reinterpret_cast<float4*>(&g_lin[(size_t)n * FTOT + lane * 8]) =
            *reinterpret_cast<const float4*>(&o[0]);
        *reinterpret_cast<float4*>(&g_lin[(size_t)n * FTOT + lane * 8 + 4]) =
            *reinterpret_cast<const float4*>(&o[4]);
    } else {
        #pragma unroll
        for (int p = 0; p < 8; p++) {
            acc[p] += __shfl_xor_sync(0xFFFFFFFFu, acc[p], 8);
            acc[p] += __shfl_xor_sync(0xFFFFFFFFu, acc[p], 16);
        }
        if (lane < 8) {
            int g = g_batch[n];
            float o[8];
            #pragma unroll
            for (int p = 0; p < 8; p++)
                o[p] = elu1(0.25f * acc[p] + bias[lane * 8 + p]);
            red_add_f4(&g_pooled[g * HID + lane * 8],
                       make_float4(o[0], o[1], o[2], o[3]));
            red_add_f4(&g_pooled[g * HID + lane * 8 + 4],
                       make_float4(o[4], o[5], o[6], o[7]));
            if (lane == 0) atomicAdd(&g_cnt[g], 1.0f);
        }
    }
}

// ---------------- classifier + log_softmax ----------------
__global__ void final_kernel(const float* __restrict__ fcw, const float* __restrict__ fcb,
                             float* __restrict__ out) {
    int g = threadIdx.x;
    if (g >= NGRAPH) return;
    float inv = 1.f / fmaxf(g_cnt[g], 1.f);
    float l[OUT_DIM];
    #pragma unroll
    for (int o = 0; o < OUT_DIM; o++) l[o] = fcb[o];
    for (int c = 0; c < HID; c++) {
        float p = g_pooled[g * HID + c] * inv;
        #pragma unroll
        for (int o = 0; o < OUT_DIM; o++) l[o] = fmaf(p, fcw[c * OUT_DIM + o], l[o]);
    }
    float mx = l[0];
    #pragma unroll
    for (int o = 1; o < OUT_DIM; o++) mx = fmaxf(mx, l[o]);
    float se = 0.f;
    #pragma unroll
    for (int o = 0; o < OUT_DIM; o++) se += expf(l[o] - mx);
    float lse = mx + logf(se);
    #pragma unroll
    for (int o = 0; o < OUT_DIM; o++) out[g * OUT_DIM + o] = l[o] - lse;
}

// ---------------- launch (fork-join: CSR build || GEMM1+alphas1) ----------------
extern "C" void kernel_launch(void* const* d_in, const int* in_sizes, int n_in,
                              void* d_out, int out_size) {
    const float* x   = (const float*)d_in[0];
    const int*   ei  = (const int*)  d_in[1];
    const int*   bat = (const int*)  d_in[2];
    const float* W1  = (const float*)d_in[3];
    const float* as1 = (const float*)d_in[4];
    const float* ad1 = (const float*)d_in[5];
    const float* b1  = (const float*)d_in[6];
    const float* W2  = (const float*)d_in[7];
    const float* as2 = (const float*)d_in[8];
    const float* ad2 = (const float*)d_in[9];
    const float* b2  = (const float*)d_in[10];
    const float* fcw = (const float*)d_in[11];
    const float* fcb = (const float*)d_in[12];
    float* out = (float*)d_out;

    int N    = in_sizes[0] / IN_DIM;
    int E    = in_sizes[1] / 2;
    int Etot = E + N;
    int nb   = (N + 255) / 256;
    const int TB = 256;
    dim3 gemm_grid(2, (N + 127) / 128);
    int gat_blocks = (N + 7) / 8;

    static cudaStream_t s_side = nullptr;
    static cudaEvent_t  ev_fork = nullptr, ev_join = nullptr;
    if (!s_side) {
        cudaStreamCreateWithFlags(&s_side, cudaStreamNonBlocking);
        cudaEventCreateWithFlags(&ev_fork, cudaEventDisableTiming);
        cudaEventCreateWithFlags(&ev_join, cudaEventDisableTiming);
    }

    // fork: CSR-build chain on side stream
    cudaEventRecord(ev_fork, 0);
    cudaStreamWaitEvent(s_side, ev_fork, 0);
    convert_edges_kernel     <<<(2 * E + TB - 1) / TB, TB, 0, s_side>>>(ei, 2 * E);
    convert_batch_init_kernel<<<nb, TB, 0, s_side>>>(bat, N);
    count_kernel<<<(E + TB - 1) / TB, TB, 0, s_side>>>(E);
    scan1_kernel<<<nb, TB, 0, s_side>>>(N);
    scan2_kernel<<<1, TB, 0, s_side>>>(nb);
    scan3_kernel<<<nb, TB, 0, s_side>>>(N, Etot);
    fill_kernel <<<(Etot + TB - 1) / TB, TB, 0, s_side>>>(E, Etot);
    cudaEventRecord(ev_join, s_side);

    // main stream: layer-1 dense path (independent of CSR)
    gemm_tf32_kernel<<<gemm_grid, TB>>>(x, W1, N, 0);
    alphas_kernel   <<<(N * HEADS * 32 + TB - 1) / TB, TB>>>(as1, ad1, N);

    // join
    cudaStreamWaitEvent(0, ev_join, 0);

    gat_warp        <<<gat_blocks, TB>>>(b1, N, 0);

    // layer 2
    gemm_tf32_kernel<<<gemm_grid, TB>>>(nullptr, W2, N, 1);
    alphas_kernel   <<<(N * HEADS * 32 + TB - 1) / TB, TB>>>(as2, ad2, N);
    gat_warp        <<<gat_blocks, TB>>>(b2, N, 1);

    // readout
    final_kernel<<<1, 64>>>(fcw, fcb, out);
}

// round 9
// speedup vs baseline: 1.1003x; 1.0728x over previous
#include <cuda_runtime.h>
#include <cuda_fp16.h>
#include <math.h>

#define IN_DIM  256
#define HID     64
#define HEADS   4
#define FTOT    256
#define OUT_DIM 10
#define NGRAPH  64
#define MAXN    50000
#define MAXE    800000

// ---------------- static scratch ----------------
__device__ __half g_feat_h[MAXN * FTOT];     // fp16 features (GEMM output, current layer)
__device__ float  g_lin   [MAXN * FTOT];     // fp32 layer-1 activated output (GEMM2 input)
__device__ float  g_as    [MAXN * HEADS];
__device__ float  g_ad    [MAXN * HEADS];
__device__ int    g_srcdst[2 * MAXE];
__device__ int    g_batch [MAXN];
__device__ int    g_deg   [MAXN];
__device__ int    g_rowptr[MAXN + 1];
__device__ int    g_cursor[MAXN];
__device__ int    g_esrc  [MAXE + MAXN];
__device__ int    g_partial[256];
__device__ float  g_pooled[NGRAPH * HID];
__device__ float  g_cnt   [NGRAPH];

// ---------------- helpers ----------------
__device__ __forceinline__ float lrelu(float v) { return v > 0.f ? v : 0.2f * v; }
__device__ __forceinline__ float elu1(float x)  { return x > 0.f ? x : expm1f(x); }
__device__ __forceinline__ float4 lrelu4(float4 a, float4 b) {
    return make_float4(lrelu(a.x + b.x), lrelu(a.y + b.y),
                       lrelu(a.z + b.z), lrelu(a.w + b.w));
}
__device__ __forceinline__ void max4(float4& m, float4 v) {
    m.x = fmaxf(m.x, v.x); m.y = fmaxf(m.y, v.y);
    m.z = fmaxf(m.z, v.z); m.w = fmaxf(m.w, v.w);
}
__device__ __forceinline__ void red_add_f4(float* addr, float4 v) {
    asm volatile("red.global.add.v4.f32 [%0], {%1, %2, %3, %4};"
                 :: "l"(addr), "f"(v.x), "f"(v.y), "f"(v.z), "f"(v.w)
                 : "memory");
}
__device__ __forceinline__ void mma_tf32(float* c, const unsigned* a, const unsigned* b) {
    asm volatile(
        "mma.sync.aligned.m16n8k8.row.col.f32.tf32.tf32.f32 "
        "{%0,%1,%2,%3},{%4,%5,%6,%7},{%8,%9},{%0,%1,%2,%3};"
        : "+f"(c[0]), "+f"(c[1]), "+f"(c[2]), "+f"(c[3])
        : "r"(a[0]), "r"(a[1]), "r"(a[2]), "r"(a[3]), "r"(b[0]), "r"(b[1]));
}
__device__ __forceinline__ void cp16(void* dst, const void* src, bool pred) {
    unsigned d = (unsigned)__cvta_generic_to_shared(dst);
    int sz = pred ? 16 : 0;
    asm volatile("cp.async.cg.shared.global [%0], [%1], 16, %2;"
                 :: "r"(d), "l"(src), "r"(sz));
}
__device__ __forceinline__ void cp_commit() { asm volatile("cp.async.commit_group;"); }
template <int W> __device__ __forceinline__ void cp_wait() {
    asm volatile("cp.async.wait_group %0;" :: "n"(W));
}

// ---------------- dtype-normalizing converters ----------------
__global__ void convert_edges_kernel(const int* __restrict__ raw, int count) {
    int nz = (raw[2 * threadIdx.x + 1] != 0);
    int any = __syncthreads_or(nz);
    int is64 = !any;
    for (int v = blockIdx.x * blockDim.x + threadIdx.x; v < count;
         v += gridDim.x * blockDim.x)
        g_srcdst[v] = is64 ? raw[2 * v] : raw[v];
}
__global__ void convert_batch_init_kernel(const int* __restrict__ raw, int count) {
    int base = count / 2;
    int w = (base | 1) + 2 * threadIdx.x;
    int nz = (raw[w] != 0);
    int any = __syncthreads_or(nz);
    int is64 = !any;
    for (int v = blockIdx.x * blockDim.x + threadIdx.x; v < count;
         v += gridDim.x * blockDim.x) {
        g_batch[v] = is64 ? raw[2 * v] : raw[v];
        g_deg[v] = 1;
    }
    int i = blockIdx.x * blockDim.x + threadIdx.x;
    if (i < NGRAPH * HID) g_pooled[i] = 0.f;
    if (i < NGRAPH) g_cnt[i] = 0.f;
}

// ---------------- CSR build ----------------
__global__ void count_kernel(int E) {
    int e = blockIdx.x * blockDim.x + threadIdx.x;
    if (e < E) atomicAdd(&g_deg[g_srcdst[E + e]], 1);
}
__global__ void scan1_kernel(int N) {
    __shared__ int s[256];
    int i = blockIdx.x * 256 + threadIdx.x;
    s[threadIdx.x] = (i < N) ? g_deg[i] : 0;
    __syncthreads();
    for (int off = 128; off; off >>= 1) {
        if (threadIdx.x < off) s[threadIdx.x] += s[threadIdx.x + off];
        __syncthreads();
    }
    if (!threadIdx.x) g_partial[blockIdx.x] = s[0];
}
__global__ void scan2_kernel(int nb) {
    __shared__ int s[256];
    int t = threadIdx.x;
    int v = (t < nb) ? g_partial[t] : 0;
    s[t] = v;
    __syncthreads();
    for (int off = 1; off < 256; off <<= 1) {
        int x = (t >= off) ? s[t - off] : 0;
        __syncthreads();
        s[t] += x;
        __syncthreads();
    }
    if (t < nb) g_partial[t] = s[t] - v;
}
__global__ void scan3_kernel(int N, int Etot) {
    __shared__ int s[256];
    int t = threadIdx.x;
    int i = blockIdx.x * 256 + t;
    int v = (i < N) ? g_deg[i] : 0;
    s[t] = v;
    __syncthreads();
    for (int off = 1; off < 256; off <<= 1) {
        int x = (t >= off) ? s[t - off] : 0;
        __syncthreads();
        s[t] += x;
        __syncthreads();
    }
    int excl = s[t] - v + g_partial[blockIdx.x];
    if (i < N) { g_rowptr[i] = excl; g_cursor[i] = excl; }
    if (i == 0) g_rowptr[N] = Etot;
}
__global__ void fill_kernel(int E, int Etot) {
    int e = blockIdx.x * blockDim.x + threadIdx.x;
    if (e >= Etot) return;
    int s, d;
    if (e < E) { s = g_srcdst[e]; d = g_srcdst[E + e]; }
    else       { s = d = e - E; }
    int pos = atomicAdd(&g_cursor[d], 1);
    g_esrc[pos] = s;
}

// ---------------- TF32 tensor-core GEMM (cvt-free; fp16-mirror-only output) ----------------
#define APAD 20
#define BPAD 136
__global__ __launch_bounds__(256, 2) void gemm_tf32_kernel(
    const float* __restrict__ Aext, const float* __restrict__ B, int M, int which)
{
    const float* __restrict__ A = which ? g_lin : Aext;

    __shared__ float As[2][128][APAD];
    __shared__ float Bs[2][16][BPAD];

    int t = threadIdx.x;
    int lane = t & 31;
    int wid = t >> 5;
    int wm = (wid & 1) * 64;
    int wn = (wid >> 1) * 32;
    int m0 = blockIdx.y * 128;
    int n0 = blockIdx.x * 128;
    int gid = lane >> 2, tig = lane & 3;

    float cacc[4][4][4];
    #pragma unroll
    for (int a = 0; a < 4; a++)
        #pragma unroll
        for (int b = 0; b < 4; b++)
            #pragma unroll
            for (int k = 0; k < 4; k++) cacc[a][b][k] = 0.f;

#define LOAD_TILES(stage, k0)                                                   \
    {                                                                           \
        _Pragma("unroll")                                                       \
        for (int r = 0; r < 2; r++) {                                           \
            int cA = t + r * 256;                                               \
            int am = cA >> 2, ak = (cA & 3) * 4;                                \
            cp16(&As[stage][am][ak],                                            \
                 &A[(size_t)(m0 + am) * 256 + (k0) + ak], (m0 + am) < M);       \
            int bk = cA >> 5, bn = (cA & 31) * 4;                               \
            cp16(&Bs[stage][bk][bn], &B[((k0) + bk) * 256 + n0 + bn], true);    \
        }                                                                       \
        cp_commit();                                                            \
    }

    LOAD_TILES(0, 0);
    for (int kt = 0; kt < 16; kt++) {
        int s = kt & 1;
        if (kt < 15) { LOAD_TILES(s ^ 1, (kt + 1) * 16); cp_wait<1>(); }
        else         { cp_wait<0>(); }
        __syncthreads();

        #pragma unroll
        for (int k8 = 0; k8 < 2; k8++) {
            int kk = k8 * 8;
            unsigned af[4][4], bf[4][2];
            #pragma unroll
            for (int mt = 0; mt < 4; mt++) {
                int row = wm + mt * 16 + gid;
                af[mt][0] = __float_as_uint(As[s][row][kk + tig]);
                af[mt][1] = __float_as_uint(As[s][row + 8][kk + tig]);
                af[mt][2] = __float_as_uint(As[s][row][kk + tig + 4]);
                af[mt][3] = __float_as_uint(As[s][row + 8][kk + tig + 4]);
            }
            #pragma unroll
            for (int nt = 0; nt < 4; nt++) {
                int col = wn + nt * 8 + gid;
                bf[nt][0] = __float_as_uint(Bs[s][kk + tig][col]);
                bf[nt][1] = __float_as_uint(Bs[s][kk + tig + 4][col]);
            }
            #pragma unroll
            for (int mt = 0; mt < 4; mt++)
                #pragma unroll
                for (int nt = 0; nt < 4; nt++)
                    mma_tf32(cacc[mt][nt], af[mt], bf[nt]);
        }
        __syncthreads();
    }
#undef LOAD_TILES

    // fp16 mirror is the ONLY feature output (alphas + gather both read it)
    #pragma unroll
    for (int mt = 0; mt < 4; mt++) {
        int row = m0 + wm + mt * 16 + gid;
        #pragma unroll
        for (int nt = 0; nt < 4; nt++) {
            int col = n0 + wn + nt * 8 + tig * 2;
            if (row < M)
                *reinterpret_cast<__half2*>(&g_feat_h[(size_t)row * 256 + col]) =
                    __floats2half2_rn(cacc[mt][nt][0], cacc[mt][nt][1]);
            if (row + 8 < M)
                *reinterpret_cast<__half2*>(&g_feat_h[(size_t)(row + 8) * 256 + col]) =
                    __floats2half2_rn(cacc[mt][nt][2], cacc[mt][nt][3]);
        }
    }
}

// ---------------- per-node attention coefficients (reads fp16 mirror) ----------------
__global__ __launch_bounds__(256) void alphas_kernel(
    const float* __restrict__ att_s, const float* __restrict__ att_d, int N)
{
    int w = (blockIdx.x * blockDim.x + threadIdx.x) >> 5;
    int lane = threadIdx.x & 31;
    if (w >= N * HEADS) return;
    int n = w >> 2, hh = w & 3;
    const __half* row = g_feat_h + (size_t)n * FTOT + hh * HID;
    const float* sv = att_s + hh * HID;
    const float* dv = att_d + hh * HID;
    float r0 = __half2float(row[lane]);
    float r1 = __half2float(row[lane + 32]);
    float s = r0 * sv[lane] + r1 * sv[lane + 32];
    float d = r0 * dv[lane] + r1 * dv[lane + 32];
    #pragma unroll
    for (int o = 16; o; o >>= 1) {
        s += __shfl_down_sync(0xFFFFFFFFu, s, o);
        d += __shfl_down_sync(0xFFFFFFFFu, d, o);
    }
    if (lane == 0) { g_as[w] = s; g_ad[w] = d; }
}

// ---------------- warp-per-node GAT (identical to round-6 passing version) ----------------
__global__ __launch_bounds__(256) void gat_warp(const float* __restrict__ bias,
                                                int N, int which)
{
    __shared__ int   s_src  [8][64];
    __shared__ float s_alpha[8][64][4];

    int w    = threadIdx.x >> 5;
    int lane = threadIdx.x & 31;
    int n    = blockIdx.x * 8 + w;
    if (n >= N) return;

    int beg = g_rowptr[n], end = g_rowptr[n + 1];
    int deg = end - beg;
    float4 adv = *reinterpret_cast<const float4*>(&g_ad[n * 4]);
    int hh = lane >> 3;

    float4 m4  = make_float4(-1e30f, -1e30f, -1e30f, -1e30f);
    float4 den = make_float4(0.f, 0.f, 0.f, 0.f);

    if (deg <= 64) {
        int s0 = (lane      < deg) ? g_esrc[beg + lane]      : -1;
        int s1 = (lane + 32 < deg) ? g_esrc[beg + lane + 32] : -1;
        if (lane < deg)      s_src[w][lane]      = s0;
        if (lane + 32 < deg) s_src[w][lane + 32] = s1;
        float4 v0 = make_float4(-1e30f, -1e30f, -1e30f, -1e30f), v1 = v0;
        if (s0 >= 0) v0 = lrelu4(*reinterpret_cast<const float4*>(&g_as[s0 * 4]), adv);
        if (s1 >= 0) v1 = lrelu4(*reinterpret_cast<const float4*>(&g_as[s1 * 4]), adv);
        m4 = v0; max4(m4, v1);
        #pragma unroll
        for (int o = 16; o; o >>= 1) {
            m4.x = fmaxf(m4.x, __shfl_xor_sync(0xFFFFFFFFu, m4.x, o));
            m4.y = fmaxf(m4.y, __shfl_xor_sync(0xFFFFFFFFu, m4.y, o));
            m4.z = fmaxf(m4.z, __shfl_xor_sync(0xFFFFFFFFu, m4.z, o));
            m4.w = fmaxf(m4.w, __shfl_xor_sync(0xFFFFFFFFu, m4.w, o));
        }
        float4 e0 = make_float4(0.f, 0.f, 0.f, 0.f), e1 = e0;
        if (s0 >= 0) e0 = make_float4(__expf(v0.x - m4.x), __expf(v0.y - m4.y),
                                      __expf(v0.z - m4.z), __expf(v0.w - m4.w));
        if (s1 >= 0) e1 = make_float4(__expf(v1.x - m4.x), __expf(v1.y - m4.y),
                                      __expf(v1.z - m4.z), __expf(v1.w - m4.w));
        den = make_float4(e0.x + e1.x, e0.y + e1.y, e0.z + e1.z, e0.w + e1.w);
        #pragma unroll
        for (int o = 16; o; o >>= 1) {
            den.x += __shfl_xor_sync(0xFFFFFFFFu, den.x, o);
            den.y += __shfl_xor_sync(0xFFFFFFFFu, den.y, o);
            den.z += __shfl_xor_sync(0xFFFFFFFFu, den.z, o);
            den.w += __shfl_xor_sync(0xFFFFFFFFu, den.w, o);
        }
        float4 inv = make_float4(1.f / (den.x + 1e-16f), 1.f / (den.y + 1e-16f),
                                 1.f / (den.z + 1e-16f), 1.f / (den.w + 1e-16f));
        if (s0 >= 0)
            *reinterpret_cast<float4*>(&s_alpha[w][lane][0]) =
                make_float4(e0.x * inv.x, e0.y * inv.y, e0.z * inv.z, e0.w * inv.w);
        if (s1 >= 0)
            *reinterpret_cast<float4*>(&s_alpha[w][lane + 32][0]) =
                make_float4(e1.x * inv.x, e1.y * inv.y, e1.z * inv.z, e1.w * inv.w);
        __syncwarp();

        float acc[8] = {0.f, 0.f, 0.f, 0.f, 0.f, 0.f, 0.f, 0.f};
        const __half* __restrict__ H = g_feat_h;
        int j = 0;
        for (; j + 4 <= deg; j += 4) {
            int t0 = s_src[w][j], t1 = s_src[w][j + 1];
            int t2 = s_src[w][j + 2], t3 = s_src[w][j + 3];
            float a0 = s_alpha[w][j][hh],     a1 = s_alpha[w][j + 1][hh];
            float a2 = s_alpha[w][j + 2][hh], a3 = s_alpha[w][j + 3][hh];
            uint4 q0 = *reinterpret_cast<const uint4*>(&H[(size_t)t0 * FTOT + lane * 8]);
            uint4 q1 = *reinterpret_cast<const uint4*>(&H[(size_t)t1 * FTOT + lane * 8]);
            uint4 q2 = *reinterpret_cast<const uint4*>(&H[(size_t)t2 * FTOT + lane * 8]);
            uint4 q3 = *reinterpret_cast<const uint4*>(&H[(size_t)t3 * FTOT + lane * 8]);
            #pragma unroll
            for (int p = 0; p < 4; p++) {
                float2 f0 = __half22float2(*(reinterpret_cast<const __half2*>(&q0) + p));
                float2 f1 = __half22float2(*(reinterpret_cast<const __half2*>(&q1) + p));
                float2 f2 = __half22float2(*(reinterpret_cast<const __half2*>(&q2) + p));
                float2 f3 = __half22float2(*(reinterpret_cast<const __half2*>(&q3) + p));
                acc[2*p]   += a0 * f0.x + a1 * f1.x + a2 * f2.x + a3 * f3.x;
                acc[2*p+1] += a0 * f0.y + a1 * f1.y + a2 * f2.y + a3 * f3.y;
            }
        }
        for (; j < deg; j++) {
            int t0 = s_src[w][j];
            float a0 = s_alpha[w][j][hh];
            uint4 q0 = *reinterpret_cast<const uint4*>(&H[(size_t)t0 * FTOT + lane * 8]);
            #pragma unroll
            for (int p = 0; p < 4; p++) {
                float2 f0 = __half22float2(*(reinterpret_cast<const __half2*>(&q0) + p));
                acc[2*p]   += a0 * f0.x;
                acc[2*p+1] += a0 * f0.y;
            }
        }

        if (which == 0) {
            float b[8];
            *reinterpret_cast<float4*>(&b[0]) =
                *reinterpret_cast<const float4*>(&bias[lane * 8]);
            *reinterpret_cast<float4*>(&b[4]) =
                *reinterpret_cast<const float4*>(&bias[lane * 8 + 4]);
            float o[8];
            #pragma unroll
            for (int p = 0; p < 8; p++) o[p] = elu1(acc[p] + b[p]);
            *reinterpret_cast<float4*>(&g_lin[(size_t)n * FTOT + lane * 8]) =
                *reinterpret_cast<const float4*>(&o[0]);
            *reinterpret_cast<float4*>(&g_lin[(size_t)n * FTOT + lane * 8 + 4]) =
                *reinterpret_cast<const float4*>(&o[4]);
        } else {
            #pragma unroll
            for (int p = 0; p < 8; p++) {
                acc[p] += __shfl_xor_sync(0xFFFFFFFFu, acc[p], 8);
                acc[p] += __shfl_xor_sync(0xFFFFFFFFu, acc[p], 16);
            }
            if (lane < 8) {
                int g = g_batch[n];
                float o[8];
                #pragma unroll
                for (int p = 0; p < 8; p++)
                    o[p] = elu1(0.25f * acc[p] + bias[lane * 8 + p]);
                red_add_f4(&g_pooled[g * HID + lane * 8],
                           make_float4(o[0], o[1], o[2], o[3]));
                red_add_f4(&g_pooled[g * HID + lane * 8 + 4],
                           make_float4(o[4], o[5], o[6], o[7]));
                if (lane == 0) atomicAdd(&g_cnt[g], 1.0f);
            }
        }
        return;
    }

    // ---- general path (deg > 64) ----
    for (int c0 = beg; c0 < end; c0 += 64) {
        int cnt = min(64, end - c0);
        int s0 = (lane < cnt) ? g_esrc[c0 + lane] : -1;
        int s1 = (lane + 32 < cnt) ? g_esrc[c0 + lane + 32] : -1;
        if (s0 >= 0) max4(m4, lrelu4(*reinterpret_cast<const float4*>(&g_as[s0 * 4]), adv));
        if (s1 >= 0) max4(m4, lrelu4(*reinterpret_cast<const float4*>(&g_as[s1 * 4]), adv));
    }
    #pragma unroll
    for (int o = 16; o; o >>= 1) {
        m4.x = fmaxf(m4.x, __shfl_xor_sync(0xFFFFFFFFu, m4.x, o));
        m4.y = fmaxf(m4.y, __shfl_xor_sync(0xFFFFFFFFu, m4.y, o));
        m4.z = fmaxf(m4.z, __shfl_xor_sync(0xFFFFFFFFu, m4.z, o));
        m4.w = fmaxf(m4.w, __shfl_xor_sync(0xFFFFFFFFu, m4.w, o));
    }
    for (int c0 = beg; c0 < end; c0 += 64) {
        int cnt = min(64, end - c0);
        int s0 = (lane < cnt) ? g_esrc[c0 + lane] : -1;
        int s1 = (lane + 32 < cnt) ? g_esrc[c0 + lane + 32] : -1;
        if (s0 >= 0) {
            float4 v = lrelu4(*reinterpret_cast<const float4*>(&g_as[s0 * 4]), adv);
            den.x += __expf(v.x - m4.x); den.y += __expf(v.y - m4.y);
            den.z += __expf(v.z - m4.z); den.w += __expf(v.w - m4.w);
        }
        if (s1 >= 0) {
            float4 v = lrelu4(*reinterpret_cast<const float4*>(&g_as[s1 * 4]), adv);
            den.x += __expf(v.x - m4.x); den.y += __expf(v.y - m4.y);
            den.z += __expf(v.z - m4.z); den.w += __expf(v.w - m4.w);
        }
    }
    #pragma unroll
    for (int o = 16; o; o >>= 1) {
        den.x += __shfl_xor_sync(0xFFFFFFFFu, den.x, o);
        den.y += __shfl_xor_sync(0xFFFFFFFFu, den.y, o);
        den.z += __shfl_xor_sync(0xFFFFFFFFu, den.z, o);
        den.w += __shfl_xor_sync(0xFFFFFFFFu, den.w, o);
    }
    float4 inv = make_float4(1.f / (den.x + 1e-16f), 1.f / (den.y + 1e-16f),
                             1.f / (den.z + 1e-16f), 1.f / (den.w + 1e-16f));

    float acc[8] = {0.f, 0.f, 0.f, 0.f, 0.f, 0.f, 0.f, 0.f};
    const __half* __restrict__ H = g_feat_h;
    for (int c0 = beg; c0 < end; c0 += 64) {
        int cnt = min(64, end - c0);
        __syncwarp();
        #pragma unroll
        for (int r = 0; r < 2; r++) {
            int i = lane + r * 32;
            if (i < cnt) {
                int s = g_esrc[c0 + i];
                s_src[w][i] = s;
                float4 v = lrelu4(*reinterpret_cast<const float4*>(&g_as[s * 4]), adv);
                *reinterpret_cast<float4*>(&s_alpha[w][i][0]) =
                    make_float4(__expf(v.x - m4.x) * inv.x, __expf(v.y - m4.y) * inv.y,
                                __expf(v.z - m4.z) * inv.z, __expf(v.w - m4.w) * inv.w);
            }
        }
        __syncwarp();
        int j = 0;
        for (; j + 4 <= cnt; j += 4) {
            int t0 = s_src[w][j], t1 = s_src[w][j+1], t2 = s_src[w][j+2], t3 = s_src[w][j+3];
            float a0 = s_alpha[w][j][hh],   a1 = s_alpha[w][j+1][hh];
            float a2 = s_alpha[w][j+2][hh], a3 = s_alpha[w][j+3][hh];
            uint4 q0 = *reinterpret_cast<const uint4*>(&H[(size_t)t0 * FTOT + lane * 8]);
            uint4 q1 = *reinterpret_cast<const uint4*>(&H[(size_t)t1 * FTOT + lane * 8]);
            uint4 q2 = *reinterpret_cast<const uint4*>(&H[(size_t)t2 * FTOT + lane * 8]);
            uint4 q3 = *reinterpret_cast<const uint4*>(&H[(size_t)t3 * FTOT + lane * 8]);
            #pragma unroll
            for (int p = 0; p < 4; p++) {
                float2 f0 = __half22float2(*(reinterpret_cast<const __half2*>(&q0) + p));
                float2 f1 = __half22float2(*(reinterpret_cast<const __half2*>(&q1) + p));
                float2 f2 = __half22float2(*(reinterpret_cast<const __half2*>(&q2) + p));
                float2 f3 = __half22float2(*(reinterpret_cast<const __half2*>(&q3) + p));
                acc[2*p]   += a0 * f0.x + a1 * f1.x + a2 * f2.x + a3 * f3.x;
                acc[2*p+1] += a0 * f0.y + a1 * f1.y + a2 * f2.y + a3 * f3.y;
            }
        }
        for (; j < cnt; j++) {
            int s = s_src[w][j];
            float a = s_alpha[w][j][hh];
            uint4 q = *reinterpret_cast<const uint4*>(&H[(size_t)s * FTOT + lane * 8]);
            #pragma unroll
            for (int p = 0; p < 4; p++) {
                float2 f = __half22float2(*(reinterpret_cast<const __half2*>(&q) + p));
                acc[2*p]   += a * f.x;
                acc[2*p+1] += a * f.y;
            }
        }
    }

    if (which == 0) {
        float o[8];
        #pragma unroll
        for (int p = 0; p < 8; p++) o[p] = elu1(acc[p] + bias[lane * 8 + p]);
        *reinterpret_cast<float4*>(&g_lin[(size_t)n * FTOT + lane * 8]) =
            *reinterpret_cast<const float4*>(&o[0]);
        *reinterpret_cast<float4*>(&g_lin[(size_t)n * FTOT + lane * 8 + 4]) =
            *reinterpret_cast<const float4*>(&o[4]);
    } else {
        #pragma unroll
        for (int p = 0; p < 8; p++) {
            acc[p] += __shfl_xor_sync(0xFFFFFFFFu, acc[p], 8);
            acc[p] += __shfl_xor_sync(0xFFFFFFFFu, acc[p], 16);
        }
        if (lane < 8) {
            int g = g_batch[n];
            float o[8];
            #pragma unroll
            for (int p = 0; p < 8; p++)
                o[p] = elu1(0.25f * acc[p] + bias[lane * 8 + p]);
            red_add_f4(&g_pooled[g * HID + lane * 8],
                       make_float4(o[0], o[1], o[2], o[3]));
            red_add_f4(&g_pooled[g * HID + lane * 8 + 4],
                       make_float4(o[4], o[5], o[6], o[7]));
            if (lane == 0) atomicAdd(&g_cnt[g], 1.0f);
        }
    }
}

// ---------------- classifier + log_softmax ----------------
__global__ void final_kernel(const float* __restrict__ fcw, const float* __restrict__ fcb,
                             float* __restrict__ out) {
    int g = threadIdx.x;
    if (g >= NGRAPH) return;
    float inv = 1.f / fmaxf(g_cnt[g], 1.f);
    float l[OUT_DIM];
    #pragma unroll
    for (int o = 0; o < OUT_DIM; o++) l[o] = fcb[o];
    for (int c = 0; c < HID; c++) {
        float p = g_pooled[g * HID + c] * inv;
        #pragma unroll
        for (int o = 0; o < OUT_DIM; o++) l[o] = fmaf(p, fcw[c * OUT_DIM + o], l[o]);
    }
    float mx = l[0];
    #pragma unroll
    for (int o = 1; o < OUT_DIM; o++) mx = fmaxf(mx, l[o]);
    float se = 0.f;
    #pragma unroll
    for (int o = 0; o < OUT_DIM; o++) se += expf(l[o] - mx);
    float lse = mx + logf(se);
    #pragma unroll
    for (int o = 0; o < OUT_DIM; o++) out[g * OUT_DIM + o] = l[o] - lse;
}

// ---------------- launch (fork-join: CSR build || GEMM1+alphas1) ----------------
extern "C" void kernel_launch(void* const* d_in, const int* in_sizes, int n_in,
                              void* d_out, int out_size) {
    const float* x   = (const float*)d_in[0];
    const int*   ei  = (const int*)  d_in[1];
    const int*   bat = (const int*)  d_in[2];
    const float* W1  = (const float*)d_in[3];
    const float* as1 = (const float*)d_in[4];
    const float* ad1 = (const float*)d_in[5];
    const float* b1  = (const float*)d_in[6];
    const float* W2  = (const float*)d_in[7];
    const float* as2 = (const float*)d_in[8];
    const float* ad2 = (const float*)d_in[9];
    const float* b2  = (const float*)d_in[10];
    const float* fcw = (const float*)d_in[11];
    const float* fcb = (const float*)d_in[12];
    float* out = (float*)d_out;

    int N    = in_sizes[0] / IN_DIM;
    int E    = in_sizes[1] / 2;
    int Etot = E + N;
    int nb   = (N + 255) / 256;
    const int TB = 256;
    dim3 gemm_grid(2, (N + 127) / 128);
    int gat_blocks = (N + 7) / 8;

    static cudaStream_t s_side = nullptr;
    static cudaEvent_t  ev_fork = nullptr, ev_join = nullptr;
    if (!s_side) {
        cudaStreamCreateWithFlags(&s_side, cudaStreamNonBlocking);
        cudaEventCreateWithFlags(&ev_fork, cudaEventDisableTiming);
        cudaEventCreateWithFlags(&ev_join, cudaEventDisableTiming);
    }

    // fork: CSR-build chain on side stream
    cudaEventRecord(ev_fork, 0);
    cudaStreamWaitEvent(s_side, ev_fork, 0);
    convert_edges_kernel     <<<(2 * E + TB - 1) / TB, TB, 0, s_side>>>(ei, 2 * E);
    convert_batch_init_kernel<<<nb, TB, 0, s_side>>>(bat, N);
    count_kernel<<<(E + TB - 1) / TB, TB, 0, s_side>>>(E);
    scan1_kernel<<<nb, TB, 0, s_side>>>(N);
    scan2_kernel<<<1, TB, 0, s_side>>>(nb);
    scan3_kernel<<<nb, TB, 0, s_side>>>(N, Etot);
    fill_kernel <<<(Etot + TB - 1) / TB, TB, 0, s_side>>>(E, Etot);
    cudaEventRecord(ev_join, s_side);

    // main stream: layer-1 dense path
    gemm_tf32_kernel<<<gemm_grid, TB>>>(x, W1, N, 0);
    alphas_kernel   <<<(N * HEADS * 32 + TB - 1) / TB, TB>>>(as1, ad1, N);

    // join
    cudaStreamWaitEvent(0, ev_join, 0);

    gat_warp<<<gat_blocks, TB>>>(b1, N, 0);

    // layer 2
    gemm_tf32_kernel<<<gemm_grid, TB>>>(nullptr, W2, N, 1);
    alphas_kernel   <<<(N * HEADS * 32 + TB - 1) / TB, TB>>>(as2, ad2, N);
    gat_warp<<<gat_blocks, TB>>>(b2, N, 1);

    // readout
    final_kernel<<<1, 64>>>(fcw, fcb, out);
}